// round 7
// baseline (speedup 1.0000x reference)
#include <cuda_runtime.h>
#include <cuda_bf16.h>
#include <math.h>
#include <stdint.h>

typedef __nv_bfloat16 bf16;

#define BB     2
#define NN     2048
#define DIM    1024
#define HH     16
#define DH     64
#define INNER  1024
#define ROWS   (BB*NN)       // 4096
#define NQKV   3072
#define KD     1024
#define LN_EPS   1e-5f
#define ATTN_EPS 1e-8f
#define SCALE    0.125f
#define SCL2E    0.1803368801111244f   // SCALE * log2(e)

// ---------------------------------------------------------------------------
// Scratch (device globals)
// ---------------------------------------------------------------------------
__device__ bf16 g_xn_hi[ROWS * DIM];
__device__ bf16 g_xn_lo[ROWS * DIM];
__device__ bf16 g_wqT_hi[NQKV * KD];
__device__ bf16 g_wqT_lo[NQKV * KD];
__device__ bf16 g_woT_hi[DIM * KD];
__device__ bf16 g_woT_lo[DIM * KD];
__device__ bf16 g_q_hi[BB*HH*NN*DH];
__device__ bf16 g_q_lo[BB*HH*NN*DH];
__device__ bf16 g_k_hi[BB*HH*NN*DH];
__device__ bf16 g_k_lo[BB*HH*NN*DH];
__device__ bf16 g_v_hi[BB*HH*NN*DH];
__device__ bf16 g_v_lo[BB*HH*NN*DH];
__device__ bf16 g_o_hi[ROWS * INNER];
__device__ bf16 g_o_lo[ROWS * INNER];

// ---------------------------------------------------------------------------
// Helpers
// ---------------------------------------------------------------------------
__device__ __forceinline__ uint32_t smem_u32(const void* p) {
    uint32_t a;
    asm("{ .reg .u64 t; cvta.to.shared.u64 t, %1; cvt.u32.u64 %0, t; }" : "=r"(a) : "l"(p));
    return a;
}
#define SWZ128(x) ((x) ^ (((x) >> 3) & 0x70))

__device__ __forceinline__ void cp16(uint32_t dst, const void* src) {
    size_t g = __cvta_generic_to_global(src);
    asm volatile("cp.async.cg.shared.global [%0], [%1], 16;" :: "r"(dst), "l"(g) : "memory");
}
__device__ __forceinline__ void cp_commit() { asm volatile("cp.async.commit_group;" ::: "memory"); }
__device__ __forceinline__ void cp_wait0()  { asm volatile("cp.async.wait_group 0;"  ::: "memory"); }
__device__ __forceinline__ void cp_wait1()  { asm volatile("cp.async.wait_group 1;"  ::: "memory"); }

__device__ __forceinline__ void ldsm4(uint32_t* r, uint32_t a) {
    asm volatile("ldmatrix.sync.aligned.m8n8.x4.shared.b16 {%0,%1,%2,%3}, [%4];"
        : "=r"(r[0]),"=r"(r[1]),"=r"(r[2]),"=r"(r[3]) : "r"(a));
}
__device__ __forceinline__ void ldsm4t(uint32_t* r, uint32_t a) {
    asm volatile("ldmatrix.sync.aligned.m8n8.x4.trans.shared.b16 {%0,%1,%2,%3}, [%4];"
        : "=r"(r[0]),"=r"(r[1]),"=r"(r[2]),"=r"(r[3]) : "r"(a));
}
__device__ __forceinline__ void mma16816(float* c, const uint32_t* a, const uint32_t* b) {
    asm volatile("mma.sync.aligned.m16n8k16.row.col.f32.bf16.bf16.f32 "
        "{%0,%1,%2,%3}, {%4,%5,%6,%7}, {%8,%9}, {%0,%1,%2,%3};"
        : "+f"(c[0]),"+f"(c[1]),"+f"(c[2]),"+f"(c[3])
        : "r"(a[0]),"r"(a[1]),"r"(a[2]),"r"(a[3]), "r"(b[0]),"r"(b[1]));
}
__device__ __forceinline__ uint32_t pack2(float x, float y) {
    __nv_bfloat162 t = __floats2bfloat162_rn(x, y);
    return *(uint32_t*)&t;
}
__device__ __forceinline__ float bhi(float v) {
    return __bfloat162float(__float2bfloat16(v));
}
__device__ __forceinline__ void f2hl(float v, bf16& h, bf16& l) {
    h = __float2bfloat16(v);
    l = __float2bfloat16(v - __bfloat162float(h));
}
__device__ __forceinline__ float ex2f(float x) {
    float y; asm("ex2.approx.f32 %0, %1;" : "=f"(y) : "f"(x)); return y;
}

// ---------------------------------------------------------------------------
// LayerNorm -> bf16 hi/lo
// ---------------------------------------------------------------------------
__global__ void ln_split_kernel(const float* __restrict__ x,
                                const float* __restrict__ gamma,
                                const float* __restrict__ beta,
                                bf16* __restrict__ xh, bf16* __restrict__ xl) {
    const int row = blockIdx.x;
    const int t   = threadIdx.x;
    float4 v = ((const float4*)(x + (size_t)row * DIM))[t];
    float s  = v.x + v.y + v.z + v.w;
    float sq = v.x*v.x + v.y*v.y + v.z*v.z + v.w*v.w;
    #pragma unroll
    for (int o = 16; o > 0; o >>= 1) {
        s  += __shfl_down_sync(0xffffffffu, s,  o);
        sq += __shfl_down_sync(0xffffffffu, sq, o);
    }
    __shared__ float ws[8], wq[8], s_mu, s_rstd;
    const int lane = t & 31, wid = t >> 5;
    if (lane == 0) { ws[wid] = s; wq[wid] = sq; }
    __syncthreads();
    if (t == 0) {
        float S = 0.f, Q = 0.f;
        #pragma unroll
        for (int i = 0; i < 8; i++) { S += ws[i]; Q += wq[i]; }
        float mu = S * (1.0f / DIM);
        float var = Q * (1.0f / DIM) - mu * mu;
        s_mu = mu; s_rstd = rsqrtf(var + LN_EPS);
    }
    __syncthreads();
    const float mu = s_mu, rstd = s_rstd;
    float4 g = ((const float4*)gamma)[t];
    float4 b = ((const float4*)beta)[t];
    float y0 = (v.x-mu)*rstd*g.x + b.x, y1 = (v.y-mu)*rstd*g.y + b.y;
    float y2 = (v.z-mu)*rstd*g.z + b.z, y3 = (v.w-mu)*rstd*g.w + b.w;
    bf16 h0,h1,h2,h3,l0,l1,l2,l3;
    f2hl(y0,h0,l0); f2hl(y1,h1,l1); f2hl(y2,h2,l2); f2hl(y3,h3,l3);
    __nv_bfloat162* H = (__nv_bfloat162*)(xh + (size_t)row * DIM);
    __nv_bfloat162* L = (__nv_bfloat162*)(xl + (size_t)row * DIM);
    H[2*t]   = __halves2bfloat162(h0,h1);  H[2*t+1] = __halves2bfloat162(h2,h3);
    L[2*t]   = __halves2bfloat162(l0,l1);  L[2*t+1] = __halves2bfloat162(l2,l3);
}

// ---------------------------------------------------------------------------
// W[K][N] f32 -> WT hi/lo [N][K] bf16
// ---------------------------------------------------------------------------
__global__ void transpose_split_kernel(const float* __restrict__ W,
                                       bf16* __restrict__ Th, bf16* __restrict__ Tl,
                                       int Kd, int Nd) {
    __shared__ float t[32][33];
    const int n0 = blockIdx.x * 32, k0 = blockIdx.y * 32;
    const int tx = threadIdx.x, ty = threadIdx.y;
    #pragma unroll
    for (int i = 0; i < 32; i += 8)
        t[ty + i][tx] = W[(size_t)(k0 + ty + i) * Nd + n0 + tx];
    __syncthreads();
    #pragma unroll
    for (int i = 0; i < 32; i += 8) {
        float v = t[tx][ty + i];
        bf16 h, l; f2hl(v, h, l);
        const size_t idx = (size_t)(n0 + ty + i) * Kd + k0 + tx;
        Th[idx] = h; Tl[idx] = l;
    }
}

// ---------------------------------------------------------------------------
// mma.sync split-bf16 GEMM with fragment double-buffering.
// C[128 x 128] tile, BK=64, 2-stage cp.async.
// Swizzled addressing: base = SWZ128(row*128) ^ lane-col; k-step via XOR
// (column bits are < 128, so XOR == the full swizzle of the sum; ADD would
// carry into row bits — that was the Round-6 bug).
// ---------------------------------------------------------------------------
#define GBK      64
#define GTILE_B  16384
#define GBUF_B   (4*GTILE_B)
#define GEMM_SMEM (2*GBUF_B)

template<int EPI>
__global__ void __launch_bounds__(256, 1)
gemm_mma_kernel(const bf16* __restrict__ Ah, const bf16* __restrict__ Al,
                const bf16* __restrict__ Bh, const bf16* __restrict__ Bl,
                bf16* __restrict__ qh, bf16* __restrict__ ql,
                bf16* __restrict__ kh, bf16* __restrict__ kl,
                bf16* __restrict__ vh, bf16* __restrict__ vl,
                const float* __restrict__ bias, float* __restrict__ outf) {
    extern __shared__ char smem[];
    const uint32_t sb = smem_u32(smem);
    const int tid = threadIdx.x;
    const int w = tid >> 5, lane = tid & 31;
    const int wm = w >> 2, wn = w & 3;
    const int brow = blockIdx.y * 128;
    const int bcol = blockIdx.x * 128;

    const bf16* bases[4] = { Ah + (size_t)brow * KD, Al + (size_t)brow * KD,
                             Bh + (size_t)bcol * KD, Bl + (size_t)bcol * KD };

    auto load_chunk = [&](int buf, int k0) {
        const uint32_t bb = sb + buf * GBUF_B;
        #pragma unroll
        for (int i = 0; i < 16; i++) {
            const int arr = i >> 2;
            const int rem = tid + (i & 3) * 256;
            const int row = rem >> 3, c = rem & 7;
            cp16(bb + arr * GTILE_B + SWZ128(row * 128 + c * 16),
                 bases[arr] + (size_t)row * KD + k0 + c * 8);
        }
        cp_commit();
    };

    // Precomputed swizzled bases (lane column folded in via XOR)
    const int grp = lane >> 3, r8 = lane & 7;
    uint32_t aSwz[4], bSwz[2];
    #pragma unroll
    for (int mf = 0; mf < 4; mf++) {
        const int arow = wm*64 + mf*16 + (lane & 15);
        aSwz[mf] = SWZ128(arow * 128) ^ ((lane >> 4) << 4);
    }
    #pragma unroll
    for (int bt = 0; bt < 2; bt++) {
        const int brw = wn*32 + bt*16 + r8 + ((grp & 2) ? 8 : 0);
        bSwz[bt] = SWZ128(brw * 128) ^ ((grp & 1) ? 16 : 0);
    }

    uint32_t Af[2][2][4][4];   // [pipe][hi/lo][mf][reg]
    uint32_t Bf[2][2][2][4];   // [pipe][hi/lo][bt][reg]
    auto ldfrags = [&](int pb, uint32_t bb, int ks) {
        #pragma unroll
        for (int mf = 0; mf < 4; mf++) {
            const uint32_t ad = bb + (aSwz[mf] ^ (ks * 32));
            ldsm4(Af[pb][0][mf], ad);
            ldsm4(Af[pb][1][mf], ad + GTILE_B);
        }
        #pragma unroll
        for (int bt = 0; bt < 2; bt++) {
            const uint32_t bd = bb + 2*GTILE_B + (bSwz[bt] ^ (ks * 32));
            ldsm4(Bf[pb][0][bt], bd);
            ldsm4(Bf[pb][1][bt], bd + GTILE_B);
        }
    };

    float acc[4][4][4] = {};
    load_chunk(0, 0);

    for (int ch = 0; ch < KD / GBK; ch++) {
        const int cur = ch & 1;
        if (ch + 1 < KD / GBK) { load_chunk(cur ^ 1, (ch + 1) * GBK); cp_wait1(); }
        else                   { cp_wait0(); }
        __syncthreads();
        const uint32_t bb = sb + cur * GBUF_B;

        ldfrags(0, bb, 0);
        #pragma unroll
        for (int ks = 0; ks < 4; ks++) {
            const int pb = ks & 1;
            if (ks < 3) ldfrags(pb ^ 1, bb, ks + 1);
            #pragma unroll
            for (int mf = 0; mf < 4; mf++) {
                #pragma unroll
                for (int nf = 0; nf < 4; nf++) {
                    const uint32_t* bh2 = &Bf[pb][0][nf >> 1][(nf & 1) * 2];
                    const uint32_t* bl2 = &Bf[pb][1][nf >> 1][(nf & 1) * 2];
                    mma16816(acc[mf][nf], Af[pb][0][mf], bh2);
                    mma16816(acc[mf][nf], Af[pb][0][mf], bl2);
                    mma16816(acc[mf][nf], Af[pb][1][mf], bh2);
                }
            }
        }
        __syncthreads();
    }

    const int t4 = lane >> 2, t2 = (lane & 3) * 2;
    if (EPI == 0) {
        const int part = bcol >> 10;
        bf16* dh = (part == 0) ? qh : (part == 1) ? kh : vh;
        bf16* dl = (part == 0) ? ql : (part == 1) ? kl : vl;
        #pragma unroll
        for (int mf = 0; mf < 4; mf++) {
            #pragma unroll
            for (int nf = 0; nf < 4; nf++) {
                const int c0 = bcol + wn*32 + nf*8 + t2;
                const int inner = c0 & 1023;
                const int hh_ = inner >> 6, d = inner & 63;
                #pragma unroll
                for (int rr = 0; rr < 2; rr++) {
                    const int m = brow + wm*64 + mf*16 + t4 + rr*8;
                    const int bq = m >> 11, n = m & 2047;
                    const size_t idx = (((size_t)(bq*HH + hh_))*NN + n)*DH + d;
                    float v0 = acc[mf][nf][rr*2], v1 = acc[mf][nf][rr*2+1];
                    *(uint32_t*)(dh + idx) = pack2(v0, v1);
                    *(uint32_t*)(dl + idx) = pack2(v0 - bhi(v0), v1 - bhi(v1));
                }
            }
        }
    } else {
        #pragma unroll
        for (int mf = 0; mf < 4; mf++) {
            #pragma unroll
            for (int nf = 0; nf < 4; nf++) {
                const int c0 = bcol + wn*32 + nf*8 + t2;
                #pragma unroll
                for (int rr = 0; rr < 2; rr++) {
                    const int m = brow + wm*64 + mf*16 + t4 + rr*8;
                    float2 o2;
                    o2.x = acc[mf][nf][rr*2]   + bias[c0];
                    o2.y = acc[mf][nf][rr*2+1] + bias[c0+1];
                    *(float2*)(outf + (size_t)m * DIM + c0) = o2;
                }
            }
        }
    }
}

// ---------------------------------------------------------------------------
// Attention: FA2-style mma.sync, split-bf16, fragment double-buffered,
// exp fused into the PV j-loop.
// ---------------------------------------------------------------------------
#define ATILE_B   8192
#define ABUF_B    (4*ATILE_B)
#define ATTN_SMEM (2*ABUF_B)

__global__ void __launch_bounds__(256, 1)
attn_mma_kernel(const bf16* __restrict__ Qh, const bf16* __restrict__ Ql,
                const bf16* __restrict__ Kh, const bf16* __restrict__ Kl,
                const bf16* __restrict__ Vh, const bf16* __restrict__ Vl,
                bf16* __restrict__ Ohi, bf16* __restrict__ Olo) {
    extern __shared__ char smem[];
    const uint32_t sb = smem_u32(smem);
    const int tid = threadIdx.x;
    const int w = tid >> 5, lane = tid & 31;
    const int grp = lane >> 3, r8 = lane & 7;
    const int qt = blockIdx.x, hh_ = blockIdx.y, bq = blockIdx.z;
    const size_t hb = ((size_t)(bq*HH + hh_)) * NN * DH;

    // ---- Stage Q tile (128 x 64 hi/lo) ----
    {
        const bf16* qsrc[2] = { Qh + hb + (size_t)qt*128*DH, Ql + hb + (size_t)qt*128*DH };
        #pragma unroll
        for (int i = 0; i < 8; i++) {
            const int arr = i >> 2;
            const int rem = tid + (i & 3) * 256;
            const int row = rem >> 3, c = rem & 7;
            cp16(sb + arr * 16384 + SWZ128(row * 128 + c * 16),
                 qsrc[arr] + (size_t)row * DH + c * 8);
        }
        cp_commit(); cp_wait0();
    }
    __syncthreads();
    uint32_t qf[2][4][4];
    {
        const int row = w*16 + (lane & 15);
        const uint32_t rb = SWZ128(row * 128) ^ ((lane >> 4) << 4);
        #pragma unroll
        for (int ks = 0; ks < 4; ks++) {
            const uint32_t ad = sb + (rb ^ (ks * 32));
            ldsm4(qf[0][ks], ad);
            ldsm4(qf[1][ks], ad + 16384);
        }
    }
    __syncthreads();

    // Precomputed swizzled bases
    uint32_t kSwz[4];
    #pragma unroll
    for (int p = 0; p < 4; p++) {
        const int brw = p*16 + r8 + ((grp & 2) ? 8 : 0);
        kSwz[p] = SWZ128(brw * 128) ^ ((grp & 1) ? 16 : 0);
    }
    const int vrsub = r8 + ((grp & 1) ? 8 : 0);
    const uint32_t vcoff = (grp & 2) ? 16 : 0;

    const bf16* kb[4] = { Kh + hb, Kl + hb, Vh + hb, Vl + hb };
    auto load_tile = [&](int buf, int s0) {
        const uint32_t bb = sb + buf * ABUF_B;
        #pragma unroll
        for (int i = 0; i < 8; i++) {
            const int arr = i >> 1;
            const int rem = tid + (i & 1) * 256;
            const int row = rem >> 3, c = rem & 7;
            cp16(bb + arr * ATILE_B + SWZ128(row * 128 + c * 16),
                 kb[arr] + (size_t)(s0 + row) * DH + c * 8);
        }
        cp_commit();
    };

    float oacc[8][4] = {};
    float dsum0 = 0.f, dsum1 = 0.f;

    load_tile(0, 0);
    for (int t = 0; t < NN/64; t++) {
        const int cur = t & 1;
        if (t + 1 < NN/64) { load_tile(cur ^ 1, (t + 1) * 64); cp_wait1(); }
        else               { cp_wait0(); }
        __syncthreads();
        const uint32_t bb = sb + cur * ABUF_B;

        // ---- S = Q K^T with Kf prefetch ----
        float sacc[8][4] = {};
        uint32_t Kf[2][2][4][4];
        auto ldK = [&](int pb, int ks) {
            #pragma unroll
            for (int p = 0; p < 4; p++) {
                const uint32_t ad = bb + (kSwz[p] ^ (ks * 32));
                ldsm4(Kf[pb][0][p], ad);
                ldsm4(Kf[pb][1][p], ad + ATILE_B);
            }
        };
        ldK(0, 0);
        #pragma unroll
        for (int ks = 0; ks < 4; ks++) {
            const int pb = ks & 1;
            if (ks < 3) ldK(pb ^ 1, ks + 1);
            #pragma unroll
            for (int nt = 0; nt < 8; nt++) {
                const uint32_t* bh2 = &Kf[pb][0][nt >> 1][(nt & 1) * 2];
                const uint32_t* bl2 = &Kf[pb][1][nt >> 1][(nt & 1) * 2];
                mma16816(sacc[nt], qf[0][ks], bh2);
                mma16816(sacc[nt], qf[0][ks], bl2);
                mma16816(sacc[nt], qf[1][ks], bh2);
            }
        }

        // ---- O += P V : exp fused per j, Vf prefetch ----
        uint32_t Vf[2][2][4][4];
        auto ldV = [&](int pb, int j) {
            const int vrow = j*16 + vrsub;
            const uint32_t vb = SWZ128(vrow * 128) ^ vcoff;
            #pragma unroll
            for (int p = 0; p < 4; p++) {
                const uint32_t ad = bb + 2*ATILE_B + (vb ^ (p * 32));
                ldsm4t(Vf[pb][0][p], ad);
                ldsm4t(Vf[pb][1][p], ad + ATILE_B);
            }
        };
        ldV(0, 0);
        #pragma unroll
        for (int j = 0; j < 4; j++) {
            const int pb = j & 1;
            if (j < 3) ldV(pb ^ 1, j + 1);
            float pA[4], pB[4];
            #pragma unroll
            for (int e = 0; e < 4; e++) pA[e] = ex2f(sacc[2*j][e]   * SCL2E);
            #pragma unroll
            for (int e = 0; e < 4; e++) pB[e] = ex2f(sacc[2*j+1][e] * SCL2E);
            dsum0 += pA[0] + pA[1] + pB[0] + pB[1];
            dsum1 += pA[2] + pA[3] + pB[2] + pB[3];
            uint32_t pfh[4], pfl[4];
            pfh[0] = pack2(pA[0], pA[1]);  pfh[1] = pack2(pA[2], pA[3]);
            pfh[2] = pack2(pB[0], pB[1]);  pfh[3] = pack2(pB[2], pB[3]);
            pfl[0] = pack2(pA[0]-bhi(pA[0]), pA[1]-bhi(pA[1]));
            pfl[1] = pack2(pA[2]-bhi(pA[2]), pA[3]-bhi(pA[3]));
            pfl[2] = pack2(pB[0]-bhi(pB[0]), pB[1]-bhi(pB[1]));
            pfl[3] = pack2(pB[2]-bhi(pB[2]), pB[3]-bhi(pB[3]));
            #pragma unroll
            for (int nt = 0; nt < 8; nt++) {
                const uint32_t* bh2 = &Vf[pb][0][nt >> 1][(nt & 1) * 2];
                const uint32_t* bl2 = &Vf[pb][1][nt >> 1][(nt & 1) * 2];
                mma16816(oacc[nt], pfh, bh2);
                mma16816(oacc[nt], pfh, bl2);
                mma16816(oacc[nt], pfl, bh2);
            }
        }
        __syncthreads();
    }

    // ---- normalize + store hi/lo bf16 [b, n, h*64+d] ----
    dsum0 += __shfl_xor_sync(0xffffffffu, dsum0, 1);
    dsum0 += __shfl_xor_sync(0xffffffffu, dsum0, 2);
    dsum1 += __shfl_xor_sync(0xffffffffu, dsum1, 1);
    dsum1 += __shfl_xor_sync(0xffffffffu, dsum1, 2);
    const float inv0 = 1.0f / (dsum0 + ATTN_EPS);
    const float inv1 = 1.0f / (dsum1 + ATTN_EPS);

    const int t4 = lane >> 2, t2 = (lane & 3) * 2;
    #pragma unroll
    for (int nf = 0; nf < 8; nf++) {
        const int d = nf*8 + t2;
        const int n0 = qt*128 + w*16 + t4;
        float v00 = oacc[nf][0]*inv0, v01 = oacc[nf][1]*inv0;
        float v10 = oacc[nf][2]*inv1, v11 = oacc[nf][3]*inv1;
        const size_t i0 = ((size_t)(bq*NN + n0)    )*INNER + hh_*DH + d;
        const size_t i1 = ((size_t)(bq*NN + n0 + 8))*INNER + hh_*DH + d;
        *(uint32_t*)(Ohi + i0) = pack2(v00, v01);
        *(uint32_t*)(Olo + i0) = pack2(v00 - bhi(v00), v01 - bhi(v01));
        *(uint32_t*)(Ohi + i1) = pack2(v10, v11);
        *(uint32_t*)(Olo + i1) = pack2(v10 - bhi(v10), v11 - bhi(v11));
    }
}

// ---------------------------------------------------------------------------
extern "C" void kernel_launch(void* const* d_in, const int* in_sizes, int n_in,
                              void* d_out, int out_size) {
    const float* x      = (const float*)d_in[0];
    const float* gamma  = (const float*)d_in[1];
    const float* beta   = (const float*)d_in[2];
    const float* w_qkv  = (const float*)d_in[3];
    const float* w_out  = (const float*)d_in[4];
    const float* b_out  = (const float*)d_in[5];
    float* out = (float*)d_out;

    bf16 *xh,*xl,*wqh,*wql,*woh,*wol,*qh,*ql,*kh,*kl,*vh,*vl,*oh,*ol;
    cudaGetSymbolAddress((void**)&xh,  g_xn_hi);
    cudaGetSymbolAddress((void**)&xl,  g_xn_lo);
    cudaGetSymbolAddress((void**)&wqh, g_wqT_hi);
    cudaGetSymbolAddress((void**)&wql, g_wqT_lo);
    cudaGetSymbolAddress((void**)&woh, g_woT_hi);
    cudaGetSymbolAddress((void**)&wol, g_woT_lo);
    cudaGetSymbolAddress((void**)&qh,  g_q_hi);
    cudaGetSymbolAddress((void**)&ql,  g_q_lo);
    cudaGetSymbolAddress((void**)&kh,  g_k_hi);
    cudaGetSymbolAddress((void**)&kl,  g_k_lo);
    cudaGetSymbolAddress((void**)&vh,  g_v_hi);
    cudaGetSymbolAddress((void**)&vl,  g_v_lo);
    cudaGetSymbolAddress((void**)&oh,  g_o_hi);
    cudaGetSymbolAddress((void**)&ol,  g_o_lo);

    cudaFuncSetAttribute(gemm_mma_kernel<0>, cudaFuncAttributeMaxDynamicSharedMemorySize, GEMM_SMEM);
    cudaFuncSetAttribute(gemm_mma_kernel<1>, cudaFuncAttributeMaxDynamicSharedMemorySize, GEMM_SMEM);
    cudaFuncSetAttribute(attn_mma_kernel,    cudaFuncAttributeMaxDynamicSharedMemorySize, ATTN_SMEM);

    ln_split_kernel<<<ROWS, 256>>>(x, gamma, beta, xh, xl);
    transpose_split_kernel<<<dim3(NQKV/32, KD/32), dim3(32, 8)>>>(w_qkv, wqh, wql, KD, NQKV);
    transpose_split_kernel<<<dim3(DIM/32,  KD/32), dim3(32, 8)>>>(w_out, woh, wol, KD, DIM);
    gemm_mma_kernel<0><<<dim3(NQKV/128, ROWS/128), 256, GEMM_SMEM>>>(
        xh, xl, wqh, wql, qh, ql, kh, kl, vh, vl, nullptr, nullptr);
    attn_mma_kernel<<<dim3(NN/128, HH, BB), 256, ATTN_SMEM>>>(
        qh, ql, kh, kl, vh, vl, oh, ol);
    gemm_mma_kernel<1><<<dim3(DIM/128, ROWS/128), 256, GEMM_SMEM>>>(
        oh, ol, woh, wol, nullptr, nullptr, nullptr, nullptr, nullptr, nullptr, b_out, out);
}

// round 8
// speedup vs baseline: 1.0360x; 1.0360x over previous
#include <cuda_runtime.h>
#include <cuda_bf16.h>
#include <math.h>
#include <stdint.h>

typedef __nv_bfloat16 bf16;

#define BB     2
#define NN     2048
#define DIM    1024
#define HH     16
#define DH     64
#define INNER  1024
#define ROWS   (BB*NN)       // 4096
#define NQKV   3072
#define KD     1024
#define LN_EPS   1e-5f
#define ATTN_EPS 1e-8f
#define SCALE    0.125f
#define SCL2E    0.1803368801111244f   // SCALE * log2(e)

// ---------------------------------------------------------------------------
// Scratch (device globals)
// ---------------------------------------------------------------------------
__device__ bf16 g_xn_hi[ROWS * DIM];
__device__ bf16 g_xn_lo[ROWS * DIM];
__device__ bf16 g_wqT_hi[NQKV * KD];
__device__ bf16 g_wqT_lo[NQKV * KD];
__device__ bf16 g_woT_hi[DIM * KD];
__device__ bf16 g_woT_lo[DIM * KD];
__device__ bf16 g_q_hi[BB*HH*NN*DH];
__device__ bf16 g_q_lo[BB*HH*NN*DH];
__device__ bf16 g_k_hi[BB*HH*NN*DH];
__device__ bf16 g_k_lo[BB*HH*NN*DH];
__device__ bf16 g_v_hi[BB*HH*NN*DH];
__device__ bf16 g_v_lo[BB*HH*NN*DH];
__device__ bf16 g_o_hi[ROWS * INNER];
__device__ bf16 g_o_lo[ROWS * INNER];

// ---------------------------------------------------------------------------
// Helpers
// ---------------------------------------------------------------------------
__device__ __forceinline__ uint32_t smem_u32(const void* p) {
    uint32_t a;
    asm("{ .reg .u64 t; cvta.to.shared.u64 t, %1; cvt.u32.u64 %0, t; }" : "=r"(a) : "l"(p));
    return a;
}
#define SWZ128(x) ((x) ^ (((x) >> 3) & 0x70))

__device__ __forceinline__ void cp16(uint32_t dst, const void* src) {
    size_t g = __cvta_generic_to_global(src);
    asm volatile("cp.async.cg.shared.global [%0], [%1], 16;" :: "r"(dst), "l"(g) : "memory");
}
__device__ __forceinline__ void cp_commit() { asm volatile("cp.async.commit_group;" ::: "memory"); }
__device__ __forceinline__ void cp_wait0()  { asm volatile("cp.async.wait_group 0;"  ::: "memory"); }

__device__ __forceinline__ void ldsm4(uint32_t* r, uint32_t a) {
    asm volatile("ldmatrix.sync.aligned.m8n8.x4.shared.b16 {%0,%1,%2,%3}, [%4];"
        : "=r"(r[0]),"=r"(r[1]),"=r"(r[2]),"=r"(r[3]) : "r"(a));
}
__device__ __forceinline__ void ldsm4t(uint32_t* r, uint32_t a) {
    asm volatile("ldmatrix.sync.aligned.m8n8.x4.trans.shared.b16 {%0,%1,%2,%3}, [%4];"
        : "=r"(r[0]),"=r"(r[1]),"=r"(r[2]),"=r"(r[3]) : "r"(a));
}
__device__ __forceinline__ void mma16816(float* c, const uint32_t* a, const uint32_t* b) {
    asm volatile("mma.sync.aligned.m16n8k16.row.col.f32.bf16.bf16.f32 "
        "{%0,%1,%2,%3}, {%4,%5,%6,%7}, {%8,%9}, {%0,%1,%2,%3};"
        : "+f"(c[0]),"+f"(c[1]),"+f"(c[2]),"+f"(c[3])
        : "r"(a[0]),"r"(a[1]),"r"(a[2]),"r"(a[3]), "r"(b[0]),"r"(b[1]));
}
__device__ __forceinline__ uint32_t pack2(float x, float y) {
    __nv_bfloat162 t = __floats2bfloat162_rn(x, y);
    return *(uint32_t*)&t;
}
__device__ __forceinline__ float bhi(float v) {
    return __bfloat162float(__float2bfloat16(v));
}
__device__ __forceinline__ void f2hl(float v, bf16& h, bf16& l) {
    h = __float2bfloat16(v);
    l = __float2bfloat16(v - __bfloat162float(h));
}
__device__ __forceinline__ float ex2f(float x) {
    float y; asm("ex2.approx.f32 %0, %1;" : "=f"(y) : "f"(x)); return y;
}

// ---------------------------------------------------------------------------
// LayerNorm -> bf16 hi/lo
// ---------------------------------------------------------------------------
__global__ void ln_split_kernel(const float* __restrict__ x,
                                const float* __restrict__ gamma,
                                const float* __restrict__ beta,
                                bf16* __restrict__ xh, bf16* __restrict__ xl) {
    const int row = blockIdx.x;
    const int t   = threadIdx.x;
    float4 v = ((const float4*)(x + (size_t)row * DIM))[t];
    float s  = v.x + v.y + v.z + v.w;
    float sq = v.x*v.x + v.y*v.y + v.z*v.z + v.w*v.w;
    #pragma unroll
    for (int o = 16; o > 0; o >>= 1) {
        s  += __shfl_down_sync(0xffffffffu, s,  o);
        sq += __shfl_down_sync(0xffffffffu, sq, o);
    }
    __shared__ float ws[8], wq[8], s_mu, s_rstd;
    const int lane = t & 31, wid = t >> 5;
    if (lane == 0) { ws[wid] = s; wq[wid] = sq; }
    __syncthreads();
    if (t == 0) {
        float S = 0.f, Q = 0.f;
        #pragma unroll
        for (int i = 0; i < 8; i++) { S += ws[i]; Q += wq[i]; }
        float mu = S * (1.0f / DIM);
        float var = Q * (1.0f / DIM) - mu * mu;
        s_mu = mu; s_rstd = rsqrtf(var + LN_EPS);
    }
    __syncthreads();
    const float mu = s_mu, rstd = s_rstd;
    float4 g = ((const float4*)gamma)[t];
    float4 b = ((const float4*)beta)[t];
    float y0 = (v.x-mu)*rstd*g.x + b.x, y1 = (v.y-mu)*rstd*g.y + b.y;
    float y2 = (v.z-mu)*rstd*g.z + b.z, y3 = (v.w-mu)*rstd*g.w + b.w;
    bf16 h0,h1,h2,h3,l0,l1,l2,l3;
    f2hl(y0,h0,l0); f2hl(y1,h1,l1); f2hl(y2,h2,l2); f2hl(y3,h3,l3);
    __nv_bfloat162* H = (__nv_bfloat162*)(xh + (size_t)row * DIM);
    __nv_bfloat162* L = (__nv_bfloat162*)(xl + (size_t)row * DIM);
    H[2*t]   = __halves2bfloat162(h0,h1);  H[2*t+1] = __halves2bfloat162(h2,h3);
    L[2*t]   = __halves2bfloat162(l0,l1);  L[2*t+1] = __halves2bfloat162(l2,l3);
}

// ---------------------------------------------------------------------------
// W[K][N] f32 -> WT hi/lo [N][K] bf16
// ---------------------------------------------------------------------------
__global__ void transpose_split_kernel(const float* __restrict__ W,
                                       bf16* __restrict__ Th, bf16* __restrict__ Tl,
                                       int Kd, int Nd) {
    __shared__ float t[32][33];
    const int n0 = blockIdx.x * 32, k0 = blockIdx.y * 32;
    const int tx = threadIdx.x, ty = threadIdx.y;
    #pragma unroll
    for (int i = 0; i < 32; i += 8)
        t[ty + i][tx] = W[(size_t)(k0 + ty + i) * Nd + n0 + tx];
    __syncthreads();
    #pragma unroll
    for (int i = 0; i < 32; i += 8) {
        float v = t[tx][ty + i];
        bf16 h, l; f2hl(v, h, l);
        const size_t idx = (size_t)(n0 + ty + i) * Kd + k0 + tx;
        Th[idx] = h; Tl[idx] = l;
    }
}

// ---------------------------------------------------------------------------
// mma.sync split-bf16 GEMM, SINGLE-buffered smem (64KB) so that 2 CTAs fit
// per SM (cross-CTA overlap replaces intra-CTA double buffering).
// Inner loop streams A fragments to keep regs <= 128 (launch_bounds 256,2).
// ---------------------------------------------------------------------------
#define GBK      64
#define GTILE_B  16384
#define GEMM_SMEM (4*GTILE_B)   // 65536 single stage: Ah,Al,Bh,Bl

template<int EPI>
__global__ void __launch_bounds__(256, 2)
gemm_mma_kernel(const bf16* __restrict__ Ah, const bf16* __restrict__ Al,
                const bf16* __restrict__ Bh, const bf16* __restrict__ Bl,
                bf16* __restrict__ qh, bf16* __restrict__ ql,
                bf16* __restrict__ kh, bf16* __restrict__ kl,
                bf16* __restrict__ vh, bf16* __restrict__ vl,
                const float* __restrict__ bias, float* __restrict__ outf) {
    extern __shared__ char smem[];
    const uint32_t sb = smem_u32(smem);
    const int tid = threadIdx.x;
    const int w = tid >> 5, lane = tid & 31;
    const int wm = w >> 2, wn = w & 3;
    const int brow = blockIdx.y * 128;
    const int bcol = blockIdx.x * 128;

    // Loader: thread handles (row0 = tid>>3, c = tid&7), 4 sub-rows apart by 32.
    const int lrow = tid >> 3, lc = tid & 7;
    const uint32_t ldst = SWZ128(lrow * 128 + lc * 16);
    const bf16* gp0 = Ah + (size_t)(brow + lrow) * KD + lc * 8;
    const bf16* gp1 = Al + (size_t)(brow + lrow) * KD + lc * 8;
    const bf16* gp2 = Bh + (size_t)(bcol + lrow) * KD + lc * 8;
    const bf16* gp3 = Bl + (size_t)(bcol + lrow) * KD + lc * 8;

    // Fragment addressing (XOR-composable swizzled bases)
    const int grp = lane >> 3, r8 = lane & 7;
    uint32_t aSwz[4], bSwz[2];
    #pragma unroll
    for (int mf = 0; mf < 4; mf++) {
        const int arow = wm*64 + mf*16 + (lane & 15);
        aSwz[mf] = SWZ128(arow * 128) ^ ((lane >> 4) << 4);
    }
    #pragma unroll
    for (int bt = 0; bt < 2; bt++) {
        const int brw = wn*32 + bt*16 + r8 + ((grp & 2) ? 8 : 0);
        bSwz[bt] = SWZ128(brw * 128) ^ ((grp & 1) ? 16 : 0);
    }

    float acc[4][4][4] = {};

    for (int ch = 0; ch < KD / GBK; ch++) {
        __syncthreads();   // previous compute done before overwrite
        const size_t ko = (size_t)ch * GBK;
        #pragma unroll
        for (int sub = 0; sub < 4; sub++) {
            const uint32_t d = ldst + sub * 4096;
            const size_t go = (size_t)sub * 32 * KD + ko;
            cp16(sb + 0*GTILE_B + d, gp0 + go);
            cp16(sb + 1*GTILE_B + d, gp1 + go);
            cp16(sb + 2*GTILE_B + d, gp2 + go);
            cp16(sb + 3*GTILE_B + d, gp3 + go);
        }
        cp_commit(); cp_wait0();
        __syncthreads();   // publish

        #pragma unroll
        for (int ks = 0; ks < 4; ks++) {
            uint32_t Bf[2][2][4];
            #pragma unroll
            for (int bt = 0; bt < 2; bt++) {
                const uint32_t bd = sb + 2*GTILE_B + (bSwz[bt] ^ (ks * 32));
                ldsm4(Bf[0][bt], bd);
                ldsm4(Bf[1][bt], bd + GTILE_B);
            }
            #pragma unroll
            for (int mf = 0; mf < 4; mf++) {
                uint32_t Ah4[4], Al4[4];
                const uint32_t ad = sb + (aSwz[mf] ^ (ks * 32));
                ldsm4(Ah4, ad);
                ldsm4(Al4, ad + GTILE_B);
                #pragma unroll
                for (int nf = 0; nf < 4; nf++) {
                    const uint32_t* bh2 = &Bf[0][nf >> 1][(nf & 1) * 2];
                    const uint32_t* bl2 = &Bf[1][nf >> 1][(nf & 1) * 2];
                    mma16816(acc[mf][nf], Ah4, bh2);
                    mma16816(acc[mf][nf], Ah4, bl2);
                    mma16816(acc[mf][nf], Al4, bh2);
                }
            }
        }
    }

    const int t4 = lane >> 2, t2 = (lane & 3) * 2;
    if (EPI == 0) {
        const int part = bcol >> 10;
        bf16* dh = (part == 0) ? qh : (part == 1) ? kh : vh;
        bf16* dl = (part == 0) ? ql : (part == 1) ? kl : vl;
        #pragma unroll
        for (int mf = 0; mf < 4; mf++) {
            #pragma unroll
            for (int nf = 0; nf < 4; nf++) {
                const int c0 = bcol + wn*32 + nf*8 + t2;
                const int inner = c0 & 1023;
                const int hh_ = inner >> 6, d = inner & 63;
                #pragma unroll
                for (int rr = 0; rr < 2; rr++) {
                    const int m = brow + wm*64 + mf*16 + t4 + rr*8;
                    const int bq = m >> 11, n = m & 2047;
                    const size_t idx = (((size_t)(bq*HH + hh_))*NN + n)*DH + d;
                    float v0 = acc[mf][nf][rr*2], v1 = acc[mf][nf][rr*2+1];
                    *(uint32_t*)(dh + idx) = pack2(v0, v1);
                    *(uint32_t*)(dl + idx) = pack2(v0 - bhi(v0), v1 - bhi(v1));
                }
            }
        }
    } else {
        #pragma unroll
        for (int mf = 0; mf < 4; mf++) {
            #pragma unroll
            for (int nf = 0; nf < 4; nf++) {
                const int c0 = bcol + wn*32 + nf*8 + t2;
                #pragma unroll
                for (int rr = 0; rr < 2; rr++) {
                    const int m = brow + wm*64 + mf*16 + t4 + rr*8;
                    float2 o2;
                    o2.x = acc[mf][nf][rr*2]   + bias[c0];
                    o2.y = acc[mf][nf][rr*2+1] + bias[c0+1];
                    *(float2*)(outf + (size_t)m * DIM + c0) = o2;
                }
            }
        }
    }
}

// ---------------------------------------------------------------------------
// Attention: FA2-style mma.sync, split-bf16.
// Single-buffered KV smem (32KB) + dedicated Q_lo region (16KB) -> 48KB,
// 2 CTAs/SM. Q_hi fragments stay in registers; Q_lo reloaded via 1 ldsm/ks.
// ---------------------------------------------------------------------------
#define ATILE_B   8192
#define AKV_B     (4*ATILE_B)        // 32768: Kh,Kl,Vh,Vl
#define AQLO      32768              // Q_lo region offset
#define ATTN_SMEM (AKV_B + 16384)    // 49152

__global__ void __launch_bounds__(256, 2)
attn_mma_kernel(const bf16* __restrict__ Qh, const bf16* __restrict__ Ql,
                const bf16* __restrict__ Kh, const bf16* __restrict__ Kl,
                const bf16* __restrict__ Vh, const bf16* __restrict__ Vl,
                bf16* __restrict__ Ohi, bf16* __restrict__ Olo) {
    extern __shared__ char smem[];
    const uint32_t sb = smem_u32(smem);
    const int tid = threadIdx.x;
    const int w = tid >> 5, lane = tid & 31;
    const int grp = lane >> 3, r8 = lane & 7;
    const int qt = blockIdx.x, hh_ = blockIdx.y, bq = blockIdx.z;
    const size_t hb = ((size_t)(bq*HH + hh_)) * NN * DH;

    const int lrow = tid >> 3, lc = tid & 7;
    const uint32_t ldst = SWZ128(lrow * 128 + lc * 16);

    // ---- Stage Q: hi into KV region (transient), lo into its own region ----
    {
        const bf16* qsh = Qh + hb + (size_t)qt*128*DH + lc*8;
        const bf16* qsl = Ql + hb + (size_t)qt*128*DH + lc*8;
        #pragma unroll
        for (int s = 0; s < 4; s++) {
            const size_t go = (size_t)(lrow + s*32) * DH;
            cp16(sb + ldst + s*4096,        qsh + go);
            cp16(sb + AQLO + ldst + s*4096, qsl + go);
        }
        cp_commit(); cp_wait0();
    }
    __syncthreads();
    const int qrow = w*16 + (lane & 15);
    const uint32_t rb = SWZ128(qrow * 128) ^ ((lane >> 4) << 4);
    uint32_t qfh[4][4];
    #pragma unroll
    for (int ks = 0; ks < 4; ks++) ldsm4(qfh[ks], sb + (rb ^ (ks * 32)));
    // (loop-top sync below guards the KV-region overwrite)

    // K fragment row bases
    uint32_t kSwz[4];
    #pragma unroll
    for (int p = 0; p < 4; p++) {
        const int brw = p*16 + r8 + ((grp & 2) ? 8 : 0);
        kSwz[p] = SWZ128(brw * 128) ^ ((grp & 1) ? 16 : 0);
    }
    const int vrsub = r8 + ((grp & 1) ? 8 : 0);
    const uint32_t vcoff = (grp & 2) ? 16 : 0;

    // KV loader pointers (per-thread fixed offsets folded in)
    const bf16* kp0 = Kh + hb + (size_t)lrow * DH + lc*8;
    const bf16* kp1 = Kl + hb + (size_t)lrow * DH + lc*8;
    const bf16* kp2 = Vh + hb + (size_t)lrow * DH + lc*8;
    const bf16* kp3 = Vl + hb + (size_t)lrow * DH + lc*8;

    float oacc[8][4] = {};
    float dsum0 = 0.f, dsum1 = 0.f;

    for (int t = 0; t < NN/64; t++) {
        __syncthreads();   // previous compute (or Q extraction) done
        const size_t tb = (size_t)t * 64 * DH;
        #pragma unroll
        for (int sub = 0; sub < 2; sub++) {
            const uint32_t d = ldst + sub * 4096;
            const size_t go = tb + (size_t)sub * 32 * DH;
            cp16(sb + 0*ATILE_B + d, kp0 + go);
            cp16(sb + 1*ATILE_B + d, kp1 + go);
            cp16(sb + 2*ATILE_B + d, kp2 + go);
            cp16(sb + 3*ATILE_B + d, kp3 + go);
        }
        cp_commit(); cp_wait0();
        __syncthreads();

        // ---- S = Q K^T ----
        float sacc[8][4] = {};
        #pragma unroll
        for (int ks = 0; ks < 4; ks++) {
            uint32_t qfl[4];
            ldsm4(qfl, sb + AQLO + (rb ^ (ks * 32)));
            #pragma unroll
            for (int p = 0; p < 4; p++) {
                uint32_t Kh4[4], Kl4[4];
                const uint32_t ad = sb + (kSwz[p] ^ (ks * 32));
                ldsm4(Kh4, ad);
                ldsm4(Kl4, ad + ATILE_B);
                #pragma unroll
                for (int q = 0; q < 2; q++) {
                    mma16816(sacc[2*p+q], qfh[ks], &Kh4[q*2]);
                    mma16816(sacc[2*p+q], qfh[ks], &Kl4[q*2]);
                    mma16816(sacc[2*p+q], qfl,     &Kh4[q*2]);
                }
            }
        }

        // ---- O += exp(S) V ----
        #pragma unroll
        for (int j = 0; j < 4; j++) {
            float pA[4], pB[4];
            #pragma unroll
            for (int e = 0; e < 4; e++) pA[e] = ex2f(sacc[2*j][e]   * SCL2E);
            #pragma unroll
            for (int e = 0; e < 4; e++) pB[e] = ex2f(sacc[2*j+1][e] * SCL2E);
            dsum0 += pA[0] + pA[1] + pB[0] + pB[1];
            dsum1 += pA[2] + pA[3] + pB[2] + pB[3];
            uint32_t pfh[4], pfl[4];
            pfh[0] = pack2(pA[0], pA[1]);  pfh[1] = pack2(pA[2], pA[3]);
            pfh[2] = pack2(pB[0], pB[1]);  pfh[3] = pack2(pB[2], pB[3]);
            pfl[0] = pack2(pA[0]-bhi(pA[0]), pA[1]-bhi(pA[1]));
            pfl[1] = pack2(pA[2]-bhi(pA[2]), pA[3]-bhi(pA[3]));
            pfl[2] = pack2(pB[0]-bhi(pB[0]), pB[1]-bhi(pB[1]));
            pfl[3] = pack2(pB[2]-bhi(pB[2]), pB[3]-bhi(pB[3]));
            const int vrow = j*16 + vrsub;
            const uint32_t vb = SWZ128(vrow * 128) ^ vcoff;
            #pragma unroll
            for (int p = 0; p < 4; p++) {
                uint32_t Vh4[4], Vl4[4];
                const uint32_t ad = sb + 2*ATILE_B + (vb ^ (p * 32));
                ldsm4t(Vh4, ad);
                ldsm4t(Vl4, ad + ATILE_B);
                #pragma unroll
                for (int q = 0; q < 2; q++) {
                    mma16816(oacc[2*p+q], pfh, &Vh4[q*2]);
                    mma16816(oacc[2*p+q], pfh, &Vl4[q*2]);
                    mma16816(oacc[2*p+q], pfl, &Vh4[q*2]);
                }
            }
        }
    }

    // ---- normalize + store hi/lo bf16 [b, n, h*64+d] ----
    dsum0 += __shfl_xor_sync(0xffffffffu, dsum0, 1);
    dsum0 += __shfl_xor_sync(0xffffffffu, dsum0, 2);
    dsum1 += __shfl_xor_sync(0xffffffffu, dsum1, 1);
    dsum1 += __shfl_xor_sync(0xffffffffu, dsum1, 2);
    const float inv0 = 1.0f / (dsum0 + ATTN_EPS);
    const float inv1 = 1.0f / (dsum1 + ATTN_EPS);

    const int t4 = lane >> 2, t2 = (lane & 3) * 2;
    #pragma unroll
    for (int nf = 0; nf < 8; nf++) {
        const int d = nf*8 + t2;
        const int n0 = qt*128 + w*16 + t4;
        float v00 = oacc[nf][0]*inv0, v01 = oacc[nf][1]*inv0;
        float v10 = oacc[nf][2]*inv1, v11 = oacc[nf][3]*inv1;
        const size_t i0 = ((size_t)(bq*NN + n0)    )*INNER + hh_*DH + d;
        const size_t i1 = ((size_t)(bq*NN + n0 + 8))*INNER + hh_*DH + d;
        *(uint32_t*)(Ohi + i0) = pack2(v00, v01);
        *(uint32_t*)(Olo + i0) = pack2(v00 - bhi(v00), v01 - bhi(v01));
        *(uint32_t*)(Ohi + i1) = pack2(v10, v11);
        *(uint32_t*)(Olo + i1) = pack2(v10 - bhi(v10), v11 - bhi(v11));
    }
}

// ---------------------------------------------------------------------------
extern "C" void kernel_launch(void* const* d_in, const int* in_sizes, int n_in,
                              void* d_out, int out_size) {
    const float* x      = (const float*)d_in[0];
    const float* gamma  = (const float*)d_in[1];
    const float* beta   = (const float*)d_in[2];
    const float* w_qkv  = (const float*)d_in[3];
    const float* w_out  = (const float*)d_in[4];
    const float* b_out  = (const float*)d_in[5];
    float* out = (float*)d_out;

    bf16 *xh,*xl,*wqh,*wql,*woh,*wol,*qh,*ql,*kh,*kl,*vh,*vl,*oh,*ol;
    cudaGetSymbolAddress((void**)&xh,  g_xn_hi);
    cudaGetSymbolAddress((void**)&xl,  g_xn_lo);
    cudaGetSymbolAddress((void**)&wqh, g_wqT_hi);
    cudaGetSymbolAddress((void**)&wql, g_wqT_lo);
    cudaGetSymbolAddress((void**)&woh, g_woT_hi);
    cudaGetSymbolAddress((void**)&wol, g_woT_lo);
    cudaGetSymbolAddress((void**)&qh,  g_q_hi);
    cudaGetSymbolAddress((void**)&ql,  g_q_lo);
    cudaGetSymbolAddress((void**)&kh,  g_k_hi);
    cudaGetSymbolAddress((void**)&kl,  g_k_lo);
    cudaGetSymbolAddress((void**)&vh,  g_v_hi);
    cudaGetSymbolAddress((void**)&vl,  g_v_lo);
    cudaGetSymbolAddress((void**)&oh,  g_o_hi);
    cudaGetSymbolAddress((void**)&ol,  g_o_lo);

    cudaFuncSetAttribute(gemm_mma_kernel<0>, cudaFuncAttributeMaxDynamicSharedMemorySize, GEMM_SMEM);
    cudaFuncSetAttribute(gemm_mma_kernel<1>, cudaFuncAttributeMaxDynamicSharedMemorySize, GEMM_SMEM);
    cudaFuncSetAttribute(attn_mma_kernel,    cudaFuncAttributeMaxDynamicSharedMemorySize, ATTN_SMEM);

    ln_split_kernel<<<ROWS, 256>>>(x, gamma, beta, xh, xl);
    transpose_split_kernel<<<dim3(NQKV/32, KD/32), dim3(32, 8)>>>(w_qkv, wqh, wql, KD, NQKV);
    transpose_split_kernel<<<dim3(DIM/32,  KD/32), dim3(32, 8)>>>(w_out, woh, wol, KD, DIM);
    gemm_mma_kernel<0><<<dim3(NQKV/128, ROWS/128), 256, GEMM_SMEM>>>(
        xh, xl, wqh, wql, qh, ql, kh, kl, vh, vl, nullptr, nullptr);
    attn_mma_kernel<<<dim3(NN/128, HH, BB), 256, ATTN_SMEM>>>(
        qh, ql, kh, kl, vh, vl, oh, ol);
    gemm_mma_kernel<1><<<dim3(DIM/128, ROWS/128), 256, GEMM_SMEM>>>(
        oh, ol, woh, wol, nullptr, nullptr, nullptr, nullptr, nullptr, nullptr, b_out, out);
}